// round 1
// baseline (speedup 1.0000x reference)
#include <cuda_runtime.h>
#include <math.h>

// Problem constants (fixed shapes from reference)
#define BB   2
#define TT   2048
#define DIM  1024
#define NH   16
#define HD   64
#define NCH  32          // T / chunk(64)
#define MTOT (BB*TT)     // 4096
#define D3   (3*DIM)     // 3072

// Scratch (device globals: allocation-free rule)
__device__ float g_qkv[(size_t)MTOT * D3];   // [4096, 3072] row-major
__device__ float g_ctx[(size_t)MTOT * DIM];  // [4096, 1024] row-major

// ---------------------------------------------------------------------------
// SGEMM: C[M,N] = A[M,K] * B[N,K]^T   (A, B, C row-major; B stored [N,K])
// 64x64 tile, BK=16, 256 threads, 4x4 per-thread microtile.
// Shapes divide evenly for all uses here (no bounds checks needed).
// ---------------------------------------------------------------------------
__global__ void __launch_bounds__(256)
sgemm_nt(const float* __restrict__ A, const float* __restrict__ B,
         float* __restrict__ C, int M, int N, int K)
{
    const int BM = 64, BN = 64, BK = 16;
    __shared__ float As[BK][BM];   // As[k][m]
    __shared__ float Bs[BK][BN];   // Bs[k][n]

    int tid = threadIdx.x;
    int m0 = blockIdx.y * BM, n0 = blockIdx.x * BN;
    int ty = tid >> 4, tx = tid & 15;          // 16x16 thread grid
    int ldRow = tid >> 2;                      // 0..63
    int ldC4  = tid & 3;                       // float4 column in K-tile

    const float* Ap = A + (size_t)(m0 + ldRow) * K + ldC4 * 4;
    const float* Bp = B + (size_t)(n0 + ldRow) * K + ldC4 * 4;

    float acc[4][4] = {};

    for (int kk = 0; kk < K; kk += BK) {
        float4 av = *(const float4*)(Ap + kk);
        float4 bv = *(const float4*)(Bp + kk);
        __syncthreads();   // previous compute done before overwriting tiles
        As[ldC4*4+0][ldRow] = av.x;  As[ldC4*4+1][ldRow] = av.y;
        As[ldC4*4+2][ldRow] = av.z;  As[ldC4*4+3][ldRow] = av.w;
        Bs[ldC4*4+0][ldRow] = bv.x;  Bs[ldC4*4+1][ldRow] = bv.y;
        Bs[ldC4*4+2][ldRow] = bv.z;  Bs[ldC4*4+3][ldRow] = bv.w;
        __syncthreads();
#pragma unroll
        for (int kt = 0; kt < BK; kt++) {
            float4 a4 = *(const float4*)&As[kt][ty*4];
            float4 b4 = *(const float4*)&Bs[kt][tx*4];
            float a[4] = {a4.x, a4.y, a4.z, a4.w};
            float b[4] = {b4.x, b4.y, b4.z, b4.w};
#pragma unroll
            for (int i = 0; i < 4; i++)
#pragma unroll
                for (int j = 0; j < 4; j++)
                    acc[i][j] += a[i] * b[j];
        }
    }

#pragma unroll
    for (int i = 0; i < 4; i++) {
        float4 o = make_float4(acc[i][0], acc[i][1], acc[i][2], acc[i][3]);
        *(float4*)(C + (size_t)(m0 + ty*4 + i) * N + n0 + tx*4) = o;
    }
}

// ---------------------------------------------------------------------------
// Block-causal flash attention.
// Mask (causal | same 64-chunk) == query chunk c attends key chunks 0..c fully.
// One CTA per (b, h, q-chunk of 64 rows). 256 threads: 4 threads per q-row.
//   thread = r*4 + l4 ; owns S/P for k in [l4*16, l4*16+16) and O dims
//   d in [l4*16, l4*16+16).
// Q rows live in registers (replicated x4 via L1 broadcast).
// K tile: padded to 17 float4/row + XOR swizzle -> conflict-free S-phase reads.
// V tile: Gray-code column swizzle g^(g>>1) -> conflict-free PV-phase reads.
// P tile reuses the K buffer (row stride 68 floats -> conflict-free P reads).
// ---------------------------------------------------------------------------
__global__ void __launch_bounds__(256)
attn_kernel(const float* __restrict__ qkv, float* __restrict__ ctx)
{
    __shared__ float4 Ks4[64 * 17];   // K tile (swizzled); reused as P (float, stride 68)
    __shared__ float4 Vs4[64 * 16];   // V tile (Gray-swizzled columns)

    int tid = threadIdx.x;
    int r  = tid >> 2;                 // q-row within chunk, 0..63
    int l4 = tid & 3;                  // lane-of-4
    int qc = blockIdx.x % NCH;
    int h  = (blockIdx.x / NCH) % NH;
    int b  = blockIdx.x / (NCH * NH);
    int qg = qc * 64 + r;

    // Q row -> registers (16 float4)
    const float* qptr = qkv + (size_t)(b * TT + qg) * D3 + h * HD;
    float4 Q[16];
#pragma unroll
    for (int g = 0; g < 16; g++) Q[g] = *(const float4*)(qptr + g * 4);

    float O[16];
#pragma unroll
    for (int j = 0; j < 16; j++) O[j] = 0.f;
    float mrow = -INFINITY, lrow = 0.f;

    const int swzK = ((l4 & 1) << 2) | (l4 & 2);   // {0,4,2,6}: distinct banks mod 32
    float* Ps = (float*)Ks4;                       // stride 68 floats per row

    for (int kc = 0; kc <= qc; kc++) {
        __syncthreads();   // prior PV phase done before tile overwrite
        // --- load K,V tiles (each thread: 1 row, 4 float4) ---
        {
            int lk = tid >> 2;                 // tile row 0..63
            int kg = kc * 64 + lk;
            const float* kbase = qkv + (size_t)(b * TT + kg) * D3 + DIM + h * HD;
            const float* vbase = kbase + DIM;
            int swz = (((lk >> 4) & 1) << 2) | (((lk >> 5) & 1) << 1);
#pragma unroll
            for (int j = 0; j < 4; j++) {
                int g = (tid & 3) + j * 4;
                Ks4[lk * 17 + (g ^ swz)]        = *(const float4*)(kbase + g * 4);
                Vs4[lk * 16 + (g ^ (g >> 1))]   = *(const float4*)(vbase + g * 4);
            }
        }
        __syncthreads();

        // --- S = scale * Q K^T  (thread: 16 k's, full 64-dot each) ---
        float S[16];
#pragma unroll
        for (int i = 0; i < 16; i++) {
            int k = l4 * 16 + i;
            const float4* krow = &Ks4[k * 17];
            float s = 0.f;
#pragma unroll
            for (int g = 0; g < 16; g++) {
                float4 kv = krow[g ^ swzK];
                s += Q[g].x * kv.x + Q[g].y * kv.y + Q[g].z * kv.z + Q[g].w * kv.w;
            }
            S[i] = s * 0.125f;   // 1/sqrt(64)
        }

        // --- online softmax (row reduce across 4 lanes) ---
        float mloc = S[0];
#pragma unroll
        for (int i = 1; i < 16; i++) mloc = fmaxf(mloc, S[i]);
        mloc = fmaxf(mloc, __shfl_xor_sync(0xffffffffu, mloc, 1));
        mloc = fmaxf(mloc, __shfl_xor_sync(0xffffffffu, mloc, 2));
        float mnew  = fmaxf(mrow, mloc);
        float alpha = __expf(mrow - mnew);
        mrow = mnew;

        float ls = 0.f;
#pragma unroll
        for (int i = 0; i < 16; i++) { S[i] = __expf(S[i] - mnew); ls += S[i]; }
        ls += __shfl_xor_sync(0xffffffffu, ls, 1);
        ls += __shfl_xor_sync(0xffffffffu, ls, 2);
        lrow = lrow * alpha + ls;
#pragma unroll
        for (int j = 0; j < 16; j++) O[j] *= alpha;

        // --- publish P into K buffer ---
        __syncthreads();   // all S-phase K reads done
#pragma unroll
        for (int i = 0; i < 16; i++) Ps[r * 68 + l4 * 16 + i] = S[i];
        __syncthreads();

        // --- O += P V  (thread: all 64 k, its 16 d's) ---
#pragma unroll 4
        for (int k = 0; k < 64; k++) {
            float p = Ps[r * 68 + k];
            const float4* vrow = &Vs4[k * 16];
#pragma unroll
            for (int j = 0; j < 4; j++) {
                int g = l4 * 4 + j;
                float4 vv = vrow[g ^ (g >> 1)];
                O[j*4+0] += p * vv.x;  O[j*4+1] += p * vv.y;
                O[j*4+2] += p * vv.z;  O[j*4+3] += p * vv.w;
            }
        }
    }

    // --- finalize + write ctx[b*T+qg][h*64 + l4*16 .. +15] ---
    float inv = 1.f / lrow;
    float* optr = ctx + (size_t)(b * TT + qg) * DIM + h * HD + l4 * 16;
#pragma unroll
    for (int j = 0; j < 4; j++) {
        float4 o = make_float4(O[j*4+0]*inv, O[j*4+1]*inv, O[j*4+2]*inv, O[j*4+3]*inv);
        *(float4*)(optr + j * 4) = o;
    }
}

// ---------------------------------------------------------------------------
extern "C" void kernel_launch(void* const* d_in, const int* in_sizes, int n_in,
                              void* d_out, int out_size)
{
    const float* x    = (const float*)d_in[0];   // [2,2048,1024]
    const float* Wqkv = (const float*)d_in[1];   // [3072,1024]
    const float* Wout = (const float*)d_in[2];   // [1024,1024]
    float* out = (float*)d_out;                  // [2,2048,1024]

    float *qkv_ptr, *ctx_ptr;
    cudaGetSymbolAddress((void**)&qkv_ptr, g_qkv);
    cudaGetSymbolAddress((void**)&ctx_ptr, g_ctx);

    // 1) qkv = x @ Wqkv^T   [4096,3072]
    dim3 g1(D3 / 64, MTOT / 64);
    sgemm_nt<<<g1, 256>>>(x, Wqkv, qkv_ptr, MTOT, D3, DIM);

    // 2) block-causal flash attention -> ctx [4096,1024]
    attn_kernel<<<BB * NH * NCH, 256>>>(qkv_ptr, ctx_ptr);

    // 3) out = ctx @ Wout^T  [4096,1024]
    dim3 g3(DIM / 64, MTOT / 64);
    sgemm_nt<<<g3, 256>>>(ctx_ptr, Wout, out, MTOT, DIM, DIM);
}

// round 2
// speedup vs baseline: 1.0000x; 1.0000x over previous
#include <cuda_runtime.h>
#include <math.h>

// Problem constants (fixed shapes from reference)
#define BB   2
#define TT   2048
#define DIM  1024
#define NH   16
#define HD   64
#define NCH  32          // T / chunk(64)
#define MTOT (BB*TT)     // 4096
#define D3   (3*DIM)     // 3072

// Scratch (device globals: allocation-free rule)
__device__ float g_qkv[(size_t)MTOT * D3];   // [4096, 3072] row-major
__device__ float g_ctx[(size_t)MTOT * DIM];  // [4096, 1024] row-major

// ---------------------------------------------------------------------------
// SGEMM: C[M,N] = A[M,K] * B[N,K]^T   (A, B, C row-major; B stored [N,K])
// 64x64 tile, BK=16, 256 threads, 4x4 per-thread microtile.
// Shapes divide evenly for all uses here (no bounds checks needed).
// ---------------------------------------------------------------------------
__global__ void __launch_bounds__(256)
sgemm_nt(const float* __restrict__ A, const float* __restrict__ B,
         float* __restrict__ C, int M, int N, int K)
{
    const int BM = 64, BN = 64, BK = 16;
    __shared__ float As[BK][BM];   // As[k][m]
    __shared__ float Bs[BK][BN];   // Bs[k][n]

    int tid = threadIdx.x;
    int m0 = blockIdx.y * BM, n0 = blockIdx.x * BN;
    int ty = tid >> 4, tx = tid & 15;          // 16x16 thread grid
    int ldRow = tid >> 2;                      // 0..63
    int ldC4  = tid & 3;                       // float4 column in K-tile

    const float* Ap = A + (size_t)(m0 + ldRow) * K + ldC4 * 4;
    const float* Bp = B + (size_t)(n0 + ldRow) * K + ldC4 * 4;

    float acc[4][4] = {};

    for (int kk = 0; kk < K; kk += BK) {
        float4 av = *(const float4*)(Ap + kk);
        float4 bv = *(const float4*)(Bp + kk);
        __syncthreads();   // previous compute done before overwriting tiles
        As[ldC4*4+0][ldRow] = av.x;  As[ldC4*4+1][ldRow] = av.y;
        As[ldC4*4+2][ldRow] = av.z;  As[ldC4*4+3][ldRow] = av.w;
        Bs[ldC4*4+0][ldRow] = bv.x;  Bs[ldC4*4+1][ldRow] = bv.y;
        Bs[ldC4*4+2][ldRow] = bv.z;  Bs[ldC4*4+3][ldRow] = bv.w;
        __syncthreads();
#pragma unroll
        for (int kt = 0; kt < BK; kt++) {
            float4 a4 = *(const float4*)&As[kt][ty*4];
            float4 b4 = *(const float4*)&Bs[kt][tx*4];
            float a[4] = {a4.x, a4.y, a4.z, a4.w};
            float b[4] = {b4.x, b4.y, b4.z, b4.w};
#pragma unroll
            for (int i = 0; i < 4; i++)
#pragma unroll
                for (int j = 0; j < 4; j++)
                    acc[i][j] += a[i] * b[j];
        }
    }

#pragma unroll
    for (int i = 0; i < 4; i++) {
        float4 o = make_float4(acc[i][0], acc[i][1], acc[i][2], acc[i][3]);
        *(float4*)(C + (size_t)(m0 + ty*4 + i) * N + n0 + tx*4) = o;
    }
}

// ---------------------------------------------------------------------------
// Block-causal flash attention.
// Mask (causal | same 64-chunk) == query chunk c attends key chunks 0..c fully.
// One CTA per (b, h, q-chunk of 64 rows). 256 threads: 4 threads per q-row.
//   thread = r*4 + l4 ; owns S/P for k in [l4*16, l4*16+16) and O dims
//   d in [l4*16, l4*16+16).
// Q rows live in registers (replicated x4 via L1 broadcast).
// K tile: padded to 17 float4/row + XOR swizzle -> conflict-free S-phase reads.
// V tile: Gray-code column swizzle g^(g>>1) -> conflict-free PV-phase reads.
// P tile reuses the K buffer (row stride 68 floats -> conflict-free P reads).
// ---------------------------------------------------------------------------
__global__ void __launch_bounds__(256)
attn_kernel(const float* __restrict__ qkv, float* __restrict__ ctx)
{
    __shared__ float4 Ks4[64 * 17];   // K tile (swizzled); reused as P (float, stride 68)
    __shared__ float4 Vs4[64 * 16];   // V tile (Gray-swizzled columns)

    int tid = threadIdx.x;
    int r  = tid >> 2;                 // q-row within chunk, 0..63
    int l4 = tid & 3;                  // lane-of-4
    int qc = blockIdx.x % NCH;
    int h  = (blockIdx.x / NCH) % NH;
    int b  = blockIdx.x / (NCH * NH);
    int qg = qc * 64 + r;

    // Q row -> registers (16 float4)
    const float* qptr = qkv + (size_t)(b * TT + qg) * D3 + h * HD;
    float4 Q[16];
#pragma unroll
    for (int g = 0; g < 16; g++) Q[g] = *(const float4*)(qptr + g * 4);

    float O[16];
#pragma unroll
    for (int j = 0; j < 16; j++) O[j] = 0.f;
    float mrow = -INFINITY, lrow = 0.f;

    const int swzK = ((l4 & 1) << 2) | (l4 & 2);   // {0,4,2,6}: distinct banks mod 32
    float* Ps = (float*)Ks4;                       // stride 68 floats per row

    for (int kc = 0; kc <= qc; kc++) {
        __syncthreads();   // prior PV phase done before tile overwrite
        // --- load K,V tiles (each thread: 1 row, 4 float4) ---
        {
            int lk = tid >> 2;                 // tile row 0..63
            int kg = kc * 64 + lk;
            const float* kbase = qkv + (size_t)(b * TT + kg) * D3 + DIM + h * HD;
            const float* vbase = kbase + DIM;
            int swz = (((lk >> 4) & 1) << 2) | (((lk >> 5) & 1) << 1);
#pragma unroll
            for (int j = 0; j < 4; j++) {
                int g = (tid & 3) + j * 4;
                Ks4[lk * 17 + (g ^ swz)]        = *(const float4*)(kbase + g * 4);
                Vs4[lk * 16 + (g ^ (g >> 1))]   = *(const float4*)(vbase + g * 4);
            }
        }
        __syncthreads();

        // --- S = scale * Q K^T  (thread: 16 k's, full 64-dot each) ---
        float S[16];
#pragma unroll
        for (int i = 0; i < 16; i++) {
            int k = l4 * 16 + i;
            const float4* krow = &Ks4[k * 17];
            float s = 0.f;
#pragma unroll
            for (int g = 0; g < 16; g++) {
                float4 kv = krow[g ^ swzK];
                s += Q[g].x * kv.x + Q[g].y * kv.y + Q[g].z * kv.z + Q[g].w * kv.w;
            }
            S[i] = s * 0.125f;   // 1/sqrt(64)
        }

        // --- online softmax (row reduce across 4 lanes) ---
        float mloc = S[0];
#pragma unroll
        for (int i = 1; i < 16; i++) mloc = fmaxf(mloc, S[i]);
        mloc = fmaxf(mloc, __shfl_xor_sync(0xffffffffu, mloc, 1));
        mloc = fmaxf(mloc, __shfl_xor_sync(0xffffffffu, mloc, 2));
        float mnew  = fmaxf(mrow, mloc);
        float alpha = __expf(mrow - mnew);
        mrow = mnew;

        float ls = 0.f;
#pragma unroll
        for (int i = 0; i < 16; i++) { S[i] = __expf(S[i] - mnew); ls += S[i]; }
        ls += __shfl_xor_sync(0xffffffffu, ls, 1);
        ls += __shfl_xor_sync(0xffffffffu, ls, 2);
        lrow = lrow * alpha + ls;
#pragma unroll
        for (int j = 0; j < 16; j++) O[j] *= alpha;

        // --- publish P into K buffer ---
        __syncthreads();   // all S-phase K reads done
#pragma unroll
        for (int i = 0; i < 16; i++) Ps[r * 68 + l4 * 16 + i] = S[i];
        __syncthreads();

        // --- O += P V  (thread: all 64 k, its 16 d's) ---
#pragma unroll 4
        for (int k = 0; k < 64; k++) {
            float p = Ps[r * 68 + k];
            const float4* vrow = &Vs4[k * 16];
#pragma unroll
            for (int j = 0; j < 4; j++) {
                int g = l4 * 4 + j;
                float4 vv = vrow[g ^ (g >> 1)];
                O[j*4+0] += p * vv.x;  O[j*4+1] += p * vv.y;
                O[j*4+2] += p * vv.z;  O[j*4+3] += p * vv.w;
            }
        }
    }

    // --- finalize + write ctx[b*T+qg][h*64 + l4*16 .. +15] ---
    float inv = 1.f / lrow;
    float* optr = ctx + (size_t)(b * TT + qg) * DIM + h * HD + l4 * 16;
#pragma unroll
    for (int j = 0; j < 4; j++) {
        float4 o = make_float4(O[j*4+0]*inv, O[j*4+1]*inv, O[j*4+2]*inv, O[j*4+3]*inv);
        *(float4*)(optr + j * 4) = o;
    }
}

// ---------------------------------------------------------------------------
extern "C" void kernel_launch(void* const* d_in, const int* in_sizes, int n_in,
                              void* d_out, int out_size)
{
    const float* x    = (const float*)d_in[0];   // [2,2048,1024]
    const float* Wqkv = (const float*)d_in[1];   // [3072,1024]
    const float* Wout = (const float*)d_in[2];   // [1024,1024]
    float* out = (float*)d_out;                  // [2,2048,1024]

    float *qkv_ptr, *ctx_ptr;
    cudaGetSymbolAddress((void**)&qkv_ptr, g_qkv);
    cudaGetSymbolAddress((void**)&ctx_ptr, g_ctx);

    // 1) qkv = x @ Wqkv^T   [4096,3072]
    dim3 g1(D3 / 64, MTOT / 64);
    sgemm_nt<<<g1, 256>>>(x, Wqkv, qkv_ptr, MTOT, D3, DIM);

    // 2) block-causal flash attention -> ctx [4096,1024]
    attn_kernel<<<BB * NH * NCH, 256>>>(qkv_ptr, ctx_ptr);

    // 3) out = ctx @ Wout^T  [4096,1024]
    dim3 g3(DIM / 64, MTOT / 64);
    sgemm_nt<<<g3, 256>>>(ctx_ptr, Wout, out, MTOT, DIM, DIM);
}

// round 3
// speedup vs baseline: 1.0007x; 1.0006x over previous
#include <cuda_runtime.h>
#include <math.h>

// Problem constants (fixed shapes from reference)
#define BB   2
#define TT   2048
#define DIM  1024
#define NH   16
#define HD   64
#define NCH  32          // T / chunk(64)
#define MTOT (BB*TT)     // 4096
#define D3   (3*DIM)     // 3072

// Scratch (device globals: allocation-free rule)
__device__ float g_qkv[(size_t)MTOT * D3];   // [4096, 3072] row-major
__device__ float g_ctx[(size_t)MTOT * DIM];  // [4096, 1024] row-major

// ---------------------------------------------------------------------------
// SGEMM: C[M,N] = A[M,K] * B[N,K]^T   (A, B, C row-major; B stored [N,K])
// 64x64 tile, BK=16, 256 threads, 4x4 per-thread microtile.
// Shapes divide evenly for all uses here (no bounds checks needed).
// ---------------------------------------------------------------------------
__global__ void __launch_bounds__(256)
sgemm_nt(const float* __restrict__ A, const float* __restrict__ B,
         float* __restrict__ C, int M, int N, int K)
{
    const int BM = 64, BN = 64, BK = 16;
    __shared__ float As[BK][BM];   // As[k][m]
    __shared__ float Bs[BK][BN];   // Bs[k][n]

    int tid = threadIdx.x;
    int m0 = blockIdx.y * BM, n0 = blockIdx.x * BN;
    int ty = tid >> 4, tx = tid & 15;          // 16x16 thread grid
    int ldRow = tid >> 2;                      // 0..63
    int ldC4  = tid & 3;                       // float4 column in K-tile

    const float* Ap = A + (size_t)(m0 + ldRow) * K + ldC4 * 4;
    const float* Bp = B + (size_t)(n0 + ldRow) * K + ldC4 * 4;

    float acc[4][4] = {};

    for (int kk = 0; kk < K; kk += BK) {
        float4 av = *(const float4*)(Ap + kk);
        float4 bv = *(const float4*)(Bp + kk);
        __syncthreads();   // previous compute done before overwriting tiles
        As[ldC4*4+0][ldRow] = av.x;  As[ldC4*4+1][ldRow] = av.y;
        As[ldC4*4+2][ldRow] = av.z;  As[ldC4*4+3][ldRow] = av.w;
        Bs[ldC4*4+0][ldRow] = bv.x;  Bs[ldC4*4+1][ldRow] = bv.y;
        Bs[ldC4*4+2][ldRow] = bv.z;  Bs[ldC4*4+3][ldRow] = bv.w;
        __syncthreads();
#pragma unroll
        for (int kt = 0; kt < BK; kt++) {
            float4 a4 = *(const float4*)&As[kt][ty*4];
            float4 b4 = *(const float4*)&Bs[kt][tx*4];
            float a[4] = {a4.x, a4.y, a4.z, a4.w};
            float b[4] = {b4.x, b4.y, b4.z, b4.w};
#pragma unroll
            for (int i = 0; i < 4; i++)
#pragma unroll
                for (int j = 0; j < 4; j++)
                    acc[i][j] += a[i] * b[j];
        }
    }

#pragma unroll
    for (int i = 0; i < 4; i++) {
        float4 o = make_float4(acc[i][0], acc[i][1], acc[i][2], acc[i][3]);
        *(float4*)(C + (size_t)(m0 + ty*4 + i) * N + n0 + tx*4) = o;
    }
}

// ---------------------------------------------------------------------------
// Block-causal flash attention.
// Mask (causal | same 64-chunk) == query chunk c attends key chunks 0..c fully.
// One CTA per (b, h, q-chunk of 64 rows). 256 threads: 4 threads per q-row.
//   thread = r*4 + l4 ; owns S/P for k in [l4*16, l4*16+16) and O dims
//   d in [l4*16, l4*16+16).
// Q rows live in registers (replicated x4 via L1 broadcast).
// K tile: padded to 17 float4/row + XOR swizzle -> conflict-free S-phase reads.
// V tile: Gray-code column swizzle g^(g>>1) -> conflict-free PV-phase reads.
// P tile reuses the K buffer (row stride 68 floats -> conflict-free P reads).
// ---------------------------------------------------------------------------
__global__ void __launch_bounds__(256)
attn_kernel(const float* __restrict__ qkv, float* __restrict__ ctx)
{
    __shared__ float4 Ks4[64 * 17];   // K tile (swizzled); reused as P (float, stride 68)
    __shared__ float4 Vs4[64 * 16];   // V tile (Gray-swizzled columns)

    int tid = threadIdx.x;
    int r  = tid >> 2;                 // q-row within chunk, 0..63
    int l4 = tid & 3;                  // lane-of-4
    int qc = blockIdx.x % NCH;
    int h  = (blockIdx.x / NCH) % NH;
    int b  = blockIdx.x / (NCH * NH);
    int qg = qc * 64 + r;

    // Q row -> registers (16 float4)
    const float* qptr = qkv + (size_t)(b * TT + qg) * D3 + h * HD;
    float4 Q[16];
#pragma unroll
    for (int g = 0; g < 16; g++) Q[g] = *(const float4*)(qptr + g * 4);

    float O[16];
#pragma unroll
    for (int j = 0; j < 16; j++) O[j] = 0.f;
    float mrow = -INFINITY, lrow = 0.f;

    const int swzK = ((l4 & 1) << 2) | (l4 & 2);   // {0,4,2,6}: distinct banks mod 32
    float* Ps = (float*)Ks4;                       // stride 68 floats per row

    for (int kc = 0; kc <= qc; kc++) {
        __syncthreads();   // prior PV phase done before tile overwrite
        // --- load K,V tiles (each thread: 1 row, 4 float4) ---
        {
            int lk = tid >> 2;                 // tile row 0..63
            int kg = kc * 64 + lk;
            const float* kbase = qkv + (size_t)(b * TT + kg) * D3 + DIM + h * HD;
            const float* vbase = kbase + DIM;
            int swz = (((lk >> 4) & 1) << 2) | (((lk >> 5) & 1) << 1);
#pragma unroll
            for (int j = 0; j < 4; j++) {
                int g = (tid & 3) + j * 4;
                Ks4[lk * 17 + (g ^ swz)]        = *(const float4*)(kbase + g * 4);
                Vs4[lk * 16 + (g ^ (g >> 1))]   = *(const float4*)(vbase + g * 4);
            }
        }
        __syncthreads();

        // --- S = scale * Q K^T  (thread: 16 k's, full 64-dot each) ---
        float S[16];
#pragma unroll
        for (int i = 0; i < 16; i++) {
            int k = l4 * 16 + i;
            const float4* krow = &Ks4[k * 17];
            float s = 0.f;
#pragma unroll
            for (int g = 0; g < 16; g++) {
                float4 kv = krow[g ^ swzK];
                s += Q[g].x * kv.x + Q[g].y * kv.y + Q[g].z * kv.z + Q[g].w * kv.w;
            }
            S[i] = s * 0.125f;   // 1/sqrt(64)
        }

        // --- online softmax (row reduce across 4 lanes) ---
        float mloc = S[0];
#pragma unroll
        for (int i = 1; i < 16; i++) mloc = fmaxf(mloc, S[i]);
        mloc = fmaxf(mloc, __shfl_xor_sync(0xffffffffu, mloc, 1));
        mloc = fmaxf(mloc, __shfl_xor_sync(0xffffffffu, mloc, 2));
        float mnew  = fmaxf(mrow, mloc);
        float alpha = __expf(mrow - mnew);
        mrow = mnew;

        float ls = 0.f;
#pragma unroll
        for (int i = 0; i < 16; i++) { S[i] = __expf(S[i] - mnew); ls += S[i]; }
        ls += __shfl_xor_sync(0xffffffffu, ls, 1);
        ls += __shfl_xor_sync(0xffffffffu, ls, 2);
        lrow = lrow * alpha + ls;
#pragma unroll
        for (int j = 0; j < 16; j++) O[j] *= alpha;

        // --- publish P into K buffer ---
        __syncthreads();   // all S-phase K reads done
#pragma unroll
        for (int i = 0; i < 16; i++) Ps[r * 68 + l4 * 16 + i] = S[i];
        __syncthreads();

        // --- O += P V  (thread: all 64 k, its 16 d's) ---
#pragma unroll 4
        for (int k = 0; k < 64; k++) {
            float p = Ps[r * 68 + k];
            const float4* vrow = &Vs4[k * 16];
#pragma unroll
            for (int j = 0; j < 4; j++) {
                int g = l4 * 4 + j;
                float4 vv = vrow[g ^ (g >> 1)];
                O[j*4+0] += p * vv.x;  O[j*4+1] += p * vv.y;
                O[j*4+2] += p * vv.z;  O[j*4+3] += p * vv.w;
            }
        }
    }

    // --- finalize + write ctx[b*T+qg][h*64 + l4*16 .. +15] ---
    float inv = 1.f / lrow;
    float* optr = ctx + (size_t)(b * TT + qg) * DIM + h * HD + l4 * 16;
#pragma unroll
    for (int j = 0; j < 4; j++) {
        float4 o = make_float4(O[j*4+0]*inv, O[j*4+1]*inv, O[j*4+2]*inv, O[j*4+3]*inv);
        *(float4*)(optr + j * 4) = o;
    }
}

// ---------------------------------------------------------------------------
extern "C" void kernel_launch(void* const* d_in, const int* in_sizes, int n_in,
                              void* d_out, int out_size)
{
    const float* x    = (const float*)d_in[0];   // [2,2048,1024]
    const float* Wqkv = (const float*)d_in[1];   // [3072,1024]
    const float* Wout = (const float*)d_in[2];   // [1024,1024]
    float* out = (float*)d_out;                  // [2,2048,1024]

    float *qkv_ptr, *ctx_ptr;
    cudaGetSymbolAddress((void**)&qkv_ptr, g_qkv);
    cudaGetSymbolAddress((void**)&ctx_ptr, g_ctx);

    // 1) qkv = x @ Wqkv^T   [4096,3072]
    dim3 g1(D3 / 64, MTOT / 64);
    sgemm_nt<<<g1, 256>>>(x, Wqkv, qkv_ptr, MTOT, D3, DIM);

    // 2) block-causal flash attention -> ctx [4096,1024]
    attn_kernel<<<BB * NH * NCH, 256>>>(qkv_ptr, ctx_ptr);

    // 3) out = ctx @ Wout^T  [4096,1024]
    dim3 g3(DIM / 64, MTOT / 64);
    sgemm_nt<<<g3, 256>>>(ctx_ptr, Wout, out, MTOT, DIM, DIM);
}